// round 16
// baseline (speedup 1.0000x reference)
#include <cuda_runtime.h>
#include <cuda_bf16.h>
#include <cuda_fp16.h>
#include <cstdint>

// ---------------- problem-size constants ----------------
#define MAX_N 50176
#define MAX_E 800000
#define D 128

// ---------------- device scratch ----------------
__device__ __half g_A[(size_t)MAX_N * 256];   // cols [0,128)=agg, [128,256)=h
__device__ __half g_W[128 * 256];             // fused weights [n][k] fp16
__device__ int   g_deg[MAX_N];                // zero at kernel-entry invariant
__device__ int   g_start[MAX_N];
__device__ int   g_cursor[MAX_N];
__device__ int   g_csr[MAX_E];                // stores src*512+256 (byte offset)
__device__ unsigned long long g_scanState[64];

// ---------------- helpers ----------------
#define GRID_WAIT()       asm volatile("griddepcontrol.wait;" ::: "memory")
#define GRID_LAUNCH_DEP() asm volatile("griddepcontrol.launch_dependents;" ::: "memory")

__device__ __forceinline__ uint32_t smem_u32(const void* p) {
    uint32_t a;
    asm("{ .reg .u64 t; cvta.to.shared.u64 t, %1; cvt.u32.u64 %0, t; }" : "=r"(a) : "l"(p));
    return a;
}

__device__ __forceinline__ void ldmat_x4(uint32_t addr, uint32_t* r) {
    asm volatile("ldmatrix.sync.aligned.m8n8.x4.shared.b16 {%0,%1,%2,%3}, [%4];"
                 : "=r"(r[0]), "=r"(r[1]), "=r"(r[2]), "=r"(r[3]) : "r"(addr));
}

__device__ __forceinline__ void mma16816(float* d, const uint32_t* a,
                                         uint32_t b0, uint32_t b1) {
    asm volatile(
        "mma.sync.aligned.m16n8k16.row.col.f32.f16.f16.f32 "
        "{%0,%1,%2,%3}, {%4,%5,%6,%7}, {%8,%9}, {%0,%1,%2,%3};"
        : "+f"(d[0]), "+f"(d[1]), "+f"(d[2]), "+f"(d[3])
        : "r"(a[0]), "r"(a[1]), "r"(a[2]), "r"(a[3]), "r"(b0), "r"(b1));
}

#define CP_ASYNC16(dst, src) \
    asm volatile("cp.async.cg.shared.global [%0], [%1], 16;" :: "r"(dst), "l"(src))
#define CP_COMMIT() asm volatile("cp.async.commit_group;")
#define CP_WAIT(n)  asm volatile("cp.async.wait_group %0;" :: "n"(n))

__device__ __forceinline__ int probe_is32(const void* edges, unsigned long long Nval) {
    const unsigned long long* e = (const unsigned long long*)edges;
    int bad = 0;
    if (threadIdx.x < 64) bad = (e[threadIdx.x] >= Nval);
    return __syncthreads_or(bad);
}

__device__ __forceinline__ __half2 u2h(uint32_t u) { return *(const __half2*)&u; }

// ---------------- Fused prep: count | LN | W-convert (disjoint block ranges) --
__global__ void prep_kernel(const float* __restrict__ x,
                            const float* __restrict__ mask,
                            const float* __restrict__ gamma,
                            const float* __restrict__ beta,
                            const float* __restrict__ wl,
                            const float* __restrict__ wr,
                            const void* __restrict__ edges,
                            int N, int E, int cntBlks, int lnBlks) {
    GRID_LAUNCH_DEP();
    int b = blockIdx.x;
    if (b < cntBlks) {
        int is32 = probe_is32(edges, (unsigned long long)N);
        long long gtid = b * (long long)blockDim.x + threadIdx.x;
        if (is32) {
            const int* dst = (const int*)edges + E;
            int n4 = E >> 2;
            if (gtid < n4) {
                int4 v = ((const int4*)dst)[gtid];
                atomicAdd(&g_deg[v.x], 1);
                atomicAdd(&g_deg[v.y], 1);
                atomicAdd(&g_deg[v.z], 1);
                atomicAdd(&g_deg[v.w], 1);
            }
            int tail = E & 3;
            if (gtid >= n4 && gtid < n4 + tail)
                atomicAdd(&g_deg[dst[(E & ~3) + (int)(gtid - n4)]], 1);
        } else {
            const long long* dst = (const long long*)edges + E;
            int n2 = E >> 1;
            if (gtid < n2) {
                longlong2 v = ((const longlong2*)dst)[gtid];
                atomicAdd(&g_deg[(int)v.x], 1);
                atomicAdd(&g_deg[(int)v.y], 1);
            }
            if ((E & 1) && gtid == n2) atomicAdd(&g_deg[(int)dst[E - 1]], 1);
        }
        return;
    }
    if (b < cntBlks + lnBlks) {
        int warp = ((b - cntBlks) * blockDim.x + threadIdx.x) >> 5;
        int lane = threadIdx.x & 31;
        int row0 = warp * 2;
        if (row0 >= N) return;
        bool has1 = (row0 + 1) < N;
        float4 v0 = ((const float4*)(x + (size_t)row0 * D))[lane];
        float4 v1 = has1 ? ((const float4*)(x + (size_t)(row0 + 1) * D))[lane]
                         : make_float4(0.f, 0.f, 0.f, 0.f);
        float4 m0 = ((const float4*)(mask + (size_t)row0 * D))[lane];
        float4 m1 = has1 ? ((const float4*)(mask + (size_t)(row0 + 1) * D))[lane]
                         : make_float4(0.f, 0.f, 0.f, 0.f);
        float4 g = ((const float4*)gamma)[lane];
        float4 bb = ((const float4*)beta)[lane];

        float s0 = v0.x + v0.y + v0.z + v0.w;
        float q0 = v0.x * v0.x + v0.y * v0.y + v0.z * v0.z + v0.w * v0.w;
        float s1 = v1.x + v1.y + v1.z + v1.w;
        float q1 = v1.x * v1.x + v1.y * v1.y + v1.z * v1.z + v1.w * v1.w;
        #pragma unroll
        for (int o = 16; o; o >>= 1) {
            s0 += __shfl_xor_sync(0xffffffffu, s0, o);
            q0 += __shfl_xor_sync(0xffffffffu, q0, o);
            s1 += __shfl_xor_sync(0xffffffffu, s1, o);
            q1 += __shfl_xor_sync(0xffffffffu, q1, o);
        }
        float mu0  = s0 * (1.0f / D);
        float inv0 = rsqrtf(q0 * (1.0f / D) - mu0 * mu0 + 1e-5f);
        float mu1  = s1 * (1.0f / D);
        float inv1 = rsqrtf(q1 * (1.0f / D) - mu1 * mu1 + 1e-5f);

        float2 p0, p1;
        p0.x = fmaxf((v0.x - mu0) * inv0 * g.x + bb.x, 0.0f) * m0.x;
        p0.y = fmaxf((v0.y - mu0) * inv0 * g.y + bb.y, 0.0f) * m0.y;
        p1.x = fmaxf((v0.z - mu0) * inv0 * g.z + bb.z, 0.0f) * m0.z;
        p1.y = fmaxf((v0.w - mu0) * inv0 * g.w + bb.w, 0.0f) * m0.w;
        __half2* dst0 = (__half2*)(g_A + (size_t)row0 * 256 + 128 + lane * 4);
        dst0[0] = __float22half2_rn(p0);
        dst0[1] = __float22half2_rn(p1);
        if (has1) {
            p0.x = fmaxf((v1.x - mu1) * inv1 * g.x + bb.x, 0.0f) * m1.x;
            p0.y = fmaxf((v1.y - mu1) * inv1 * g.y + bb.y, 0.0f) * m1.y;
            p1.x = fmaxf((v1.z - mu1) * inv1 * g.z + bb.z, 0.0f) * m1.z;
            p1.y = fmaxf((v1.w - mu1) * inv1 * g.w + bb.w, 0.0f) * m1.w;
            __half2* dst1 = (__half2*)(g_A + (size_t)(row0 + 1) * 256 + 128 + lane * 4);
            dst1[0] = __float22half2_rn(p0);
            dst1[1] = __float22half2_rn(p1);
        }
        return;
    }
    int idx = (b - cntBlks - lnBlks) * blockDim.x + threadIdx.x;
    if (idx < 128 * 256) {
        int n = idx >> 8;
        int k = idx & 255;
        float v = (k < 128) ? wl[n * 128 + k] : wr[n * 128 + (k - 128)];
        g_W[idx] = __float2half_rn(v);
    }
}

// ---------------- single-pass decoupled-lookback scan ----------------
__global__ void scan_kernel(int N) {
    GRID_WAIT();
    GRID_LAUNCH_DEP();
    __shared__ int ws[32];
    __shared__ int s_prefix;
    __shared__ int s_total;
    int b = blockIdx.x;
    int i = b * 1024 + threadIdx.x;
    int lane = threadIdx.x & 31, wid = threadIdx.x >> 5;

    int v = (i < N) ? g_deg[i] : 0;
    if (i < N) g_deg[i] = 0;
    int incl = v;
    #pragma unroll
    for (int o = 1; o < 32; o <<= 1) {
        int t = __shfl_up_sync(0xffffffffu, incl, o);
        if (lane >= o) incl += t;
    }
    if (lane == 31) ws[wid] = incl;
    __syncthreads();
    if (wid == 0) {
        int sv = ws[lane];
        int in2 = sv;
        #pragma unroll
        for (int o = 1; o < 32; o <<= 1) {
            int t = __shfl_up_sync(0xffffffffu, in2, o);
            if (lane >= o) in2 += t;
        }
        ws[lane] = in2 - sv;
    }
    __syncthreads();
    int excl = incl - v + ws[wid];
    if (threadIdx.x == 1023) s_total = excl + v;
    __syncthreads();
    int blockSum = s_total;

    if (threadIdx.x == 0) {
        unsigned long long pack = b == 0
            ? ((2ULL << 32) | (unsigned)blockSum)
            : ((1ULL << 32) | (unsigned)blockSum);
        atomicExch(&g_scanState[b], pack);
    }

    if (wid == 0 && b > 0) {
        long long run = 0;
        int j = b - 1;
        while (true) {
            int idx = j - lane;
            unsigned long long s;
            unsigned status;
            do {
                s = (idx >= 0) ? atomicAdd(&g_scanState[idx], 0ULL)
                               : (1ULL << 32);
                status = (unsigned)(s >> 32);
            } while (__any_sync(0xffffffffu, status == 0));
            unsigned val = (unsigned)s;
            unsigned pmask = __ballot_sync(0xffffffffu, status == 2);
            if (pmask) {
                int fl = __ffs(pmask) - 1;
                long long c = (lane <= fl) ? (long long)val : 0;
                #pragma unroll
                for (int o = 16; o; o >>= 1) c += __shfl_xor_sync(0xffffffffu, c, o);
                run += c;
                break;
            } else {
                long long c = (idx >= 0) ? (long long)val : 0;
                #pragma unroll
                for (int o = 16; o; o >>= 1) c += __shfl_xor_sync(0xffffffffu, c, o);
                run += c;
                j -= 32;
            }
        }
        if (lane == 0) {
            atomicExch(&g_scanState[b], (2ULL << 32) | (unsigned)(run + blockSum));
            s_prefix = (int)run;
        }
    }
    if (b == 0 && threadIdx.x == 0) s_prefix = 0;
    __syncthreads();
    if (i < N) {
        int st = excl + s_prefix;
        g_start[i] = st;
        g_cursor[i] = st;
    }
}

// ---------------- scatter: stores src*512+256 (byte offset of h row) --------
__global__ void scatter_kernel(const void* __restrict__ edges, int E,
                               unsigned long long Nval) {
    GRID_WAIT();
    GRID_LAUNCH_DEP();
    if (blockIdx.x == 0 && threadIdx.x < 64) g_scanState[threadIdx.x] = 0ULL;
    int is32 = probe_is32(edges, Nval);
    long long gtid = blockIdx.x * (long long)blockDim.x + threadIdx.x;
    if (is32) {
        int n4 = E >> 2;
        if (gtid < n4) {
            int4 sv = ((const int4*)edges)[gtid];
            int4 dv = ((const int4*)((const int*)edges + E))[gtid];
            g_csr[atomicAdd(&g_cursor[dv.x], 1)] = (sv.x << 9) + 256;
            g_csr[atomicAdd(&g_cursor[dv.y], 1)] = (sv.y << 9) + 256;
            g_csr[atomicAdd(&g_cursor[dv.z], 1)] = (sv.z << 9) + 256;
            g_csr[atomicAdd(&g_cursor[dv.w], 1)] = (sv.w << 9) + 256;
        }
        int tail = E & 3;
        if (gtid >= n4 && gtid < n4 + tail) {
            int e = (E & ~3) + (int)(gtid - n4);
            int src = ((const int*)edges)[e];
            int dst = ((const int*)edges)[E + e];
            g_csr[atomicAdd(&g_cursor[dst], 1)] = (src << 9) + 256;
        }
    } else {
        int n2 = E >> 1;
        if (gtid < n2) {
            longlong2 sv = ((const longlong2*)edges)[gtid];
            longlong2 dv = ((const longlong2*)((const long long*)edges + E))[gtid];
            g_csr[atomicAdd(&g_cursor[(int)dv.x], 1)] = ((int)sv.x << 9) + 256;
            g_csr[atomicAdd(&g_cursor[(int)dv.y], 1)] = ((int)sv.y << 9) + 256;
        }
        if ((E & 1) && gtid == n2) {
            int src = (int)((const long long*)edges)[E - 1];
            int dst = (int)((const long long*)edges)[2 * E - 1];
            g_csr[atomicAdd(&g_cursor[dst], 1)] = (src << 9) + 256;
        }
    }
}

// ---------------- aggregation: depth-8 fp16 tree -------------------
__global__ void aggregate_kernel(int N, int E) {
    GRID_LAUNCH_DEP();
    GRID_WAIT();
    int warp = (blockIdx.x * blockDim.x + threadIdx.x) >> 5;
    int lane = threadIdx.x & 31;
    if (warp >= N) return;
    int st = g_start[warp];
    int en = (warp + 1 < N) ? g_start[warp + 1] : E;
    int d  = en - st;
    const char* hb = (const char*)g_A + lane * 8;
    float2 acc0 = make_float2(0.f, 0.f);
    float2 acc1 = make_float2(0.f, 0.f);
    int j = st;
    // 8 neighbors per iter: full fp16 depth-8 tree, ONE conversion per lane-pair
    for (; j + 8 <= en; j += 8) {
        int o0 = g_csr[j],     o1 = g_csr[j + 1], o2 = g_csr[j + 2], o3 = g_csr[j + 3];
        int o4 = g_csr[j + 4], o5 = g_csr[j + 5], o6 = g_csr[j + 6], o7 = g_csr[j + 7];
        uint2 v0 = *(const uint2*)(hb + o0);
        uint2 v1 = *(const uint2*)(hb + o1);
        uint2 v2 = *(const uint2*)(hb + o2);
        uint2 v3 = *(const uint2*)(hb + o3);
        uint2 v4 = *(const uint2*)(hb + o4);
        uint2 v5 = *(const uint2*)(hb + o5);
        uint2 v6 = *(const uint2*)(hb + o6);
        uint2 v7 = *(const uint2*)(hb + o7);
        __half2 qx = __hadd2(
            __hadd2(__hadd2(u2h(v0.x), u2h(v1.x)), __hadd2(u2h(v2.x), u2h(v3.x))),
            __hadd2(__hadd2(u2h(v4.x), u2h(v5.x)), __hadd2(u2h(v6.x), u2h(v7.x))));
        __half2 qy = __hadd2(
            __hadd2(__hadd2(u2h(v0.y), u2h(v1.y)), __hadd2(u2h(v2.y), u2h(v3.y))),
            __hadd2(__hadd2(u2h(v4.y), u2h(v5.y)), __hadd2(u2h(v6.y), u2h(v7.y))));
        float2 f;
        f = __half22float2(qx); acc0.x += f.x; acc0.y += f.y;
        f = __half22float2(qy); acc1.x += f.x; acc1.y += f.y;
    }
    if (j + 4 <= en) {
        int o0 = g_csr[j], o1 = g_csr[j + 1], o2 = g_csr[j + 2], o3 = g_csr[j + 3];
        uint2 v0 = *(const uint2*)(hb + o0);
        uint2 v1 = *(const uint2*)(hb + o1);
        uint2 v2 = *(const uint2*)(hb + o2);
        uint2 v3 = *(const uint2*)(hb + o3);
        __half2 qx = __hadd2(__hadd2(u2h(v0.x), u2h(v1.x)), __hadd2(u2h(v2.x), u2h(v3.x)));
        __half2 qy = __hadd2(__hadd2(u2h(v0.y), u2h(v1.y)), __hadd2(u2h(v2.y), u2h(v3.y)));
        float2 f;
        f = __half22float2(qx); acc0.x += f.x; acc0.y += f.y;
        f = __half22float2(qy); acc1.x += f.x; acc1.y += f.y;
        j += 4;
    }
    for (; j < en; ++j) {
        uint2 v = *(const uint2*)(hb + g_csr[j]);
        float2 a = __half22float2(u2h(v.x));
        float2 b = __half22float2(u2h(v.y));
        acc0.x += a.x; acc0.y += a.y; acc1.x += b.x; acc1.y += b.y;
    }
    float invd = 1.0f / fmaxf((float)d, 1.0f);
    acc0.x *= invd; acc0.y *= invd; acc1.x *= invd; acc1.y *= invd;
    __half2 h0 = __float22half2_rn(acc0);
    __half2 h1 = __float22half2_rn(acc1);
    uint2 pk;
    pk.x = *(uint32_t*)&h0;
    pk.y = *(uint32_t*)&h1;
    *(uint2*)((char*)g_A + (size_t)warp * 512 + lane * 8) = pk;
}

// ---------------- fp16 mma GEMM: h-chunks overlap aggregate via PDL --------
#define B_OFF  0
#define A0_OFF 65536
#define ABUF_SZ 16384
#define GSMEM_TOTAL (65536 + 2 * ABUF_SZ)

__global__ __launch_bounds__(256) void mma_gemm_kernel(const float* __restrict__ bias,
                                                       float* __restrict__ out, int N) {
    extern __shared__ char smem[];
    uint32_t sb = smem_u32(smem);
    int tid = threadIdx.x;
    int lane = tid & 31;
    int wid = tid >> 5;
    int warp_m = wid & 3;
    int warp_n = wid >> 2;
    int rowBase = blockIdx.x * 128;

    for (int idx = tid; idx < 4096; idx += 256) {
        int r  = idx >> 5;
        int ck = idx & 31;
        uint32_t off = (uint32_t)r * 512 + ((uint32_t)(ck ^ (r & 7)) << 4);
        CP_ASYNC16(sb + B_OFF + off, (const char*)(g_W + (size_t)r * 256 + ck * 8));
    }
    #define STAGE_A(c, buf)                                                        \
        for (int idx = tid; idx < 1024; idx += 256) {                              \
            int r  = idx >> 3;                                                     \
            int ck = idx & 7;                                                      \
            CP_ASYNC16(sb + A0_OFF + (buf) * ABUF_SZ + r * 128                     \
                           + ((uint32_t)(ck ^ (r & 7)) << 4),                      \
                       (const char*)(g_A + (size_t)(rowBase + r) * 256             \
                                     + (c) * 64 + ck * 8));                        \
        }
    STAGE_A(2, 0);
    CP_COMMIT();
    STAGE_A(3, 1);
    CP_COMMIT();

    float acc[2][8][4];
    #pragma unroll
    for (int i = 0; i < 2; i++)
        #pragma unroll
        for (int j = 0; j < 8; j++)
            #pragma unroll
            for (int q = 0; q < 4; q++) acc[i][j][q] = 0.0f;

    int aRow = (lane & 7) + ((lane >> 3) & 1) * 8;
    int aK8  = (lane >> 4) * 8;
    int bN   = (lane & 7) + (lane >> 4) * 8;
    int bK8  = ((lane >> 3) & 1) * 8;

    #define COMPUTE_CHUNK(gc, buf)                                                 \
        {                                                                          \
            uint32_t abase = sb + A0_OFF + (buf) * ABUF_SZ;                        \
            _Pragma("unroll")                                                      \
            for (int ks = 0; ks < 4; ++ks) {                                       \
                int kk = ks * 16;                                                  \
                uint32_t a[2][4];                                                  \
                _Pragma("unroll")                                                  \
                for (int mf = 0; mf < 2; ++mf) {                                   \
                    int row = warp_m * 32 + mf * 16 + aRow;                        \
                    int kA  = kk + aK8;                                            \
                    uint32_t addr = abase + (uint32_t)row * 128                    \
                                  + ((uint32_t)(((kA >> 3) ^ (row & 7))) << 4);    \
                    ldmat_x4(addr, a[mf]);                                         \
                }                                                                  \
                int gk = (gc) * 64 + kk;                                           \
                _Pragma("unroll")                                                  \
                for (int j = 0; j < 4; ++j) {                                      \
                    int n  = warp_n * 64 + j * 16 + bN;                            \
                    int kB = gk + bK8;                                             \
                    uint32_t addr = sb + B_OFF + (uint32_t)n * 512                 \
                                  + ((uint32_t)(((kB >> 3) ^ (n & 7))) << 4);      \
                    uint32_t b[4];                                                 \
                    ldmat_x4(addr, b);                                             \
                    mma16816(acc[0][2 * j],     a[0], b[0], b[1]);                 \
                    mma16816(acc[0][2 * j + 1], a[0], b[2], b[3]);                 \
                    mma16816(acc[1][2 * j],     a[1], b[0], b[1]);                 \
                    mma16816(acc[1][2 * j + 1], a[1], b[2], b[3]);                 \
                }                                                                  \
            }                                                                      \
        }

    CP_WAIT(1);
    __syncthreads();
    COMPUTE_CHUNK(2, 0);
    CP_WAIT(0);
    __syncthreads();
    COMPUTE_CHUNK(3, 1);
    __syncthreads();

    GRID_WAIT();
    STAGE_A(0, 0);
    CP_COMMIT();
    STAGE_A(1, 1);
    CP_COMMIT();
    CP_WAIT(1);
    __syncthreads();
    COMPUTE_CHUNK(0, 0);
    CP_WAIT(0);
    __syncthreads();
    COMPUTE_CHUNK(1, 1);

    float2 bcol[8];
    #pragma unroll
    for (int nf = 0; nf < 8; ++nf) {
        int col = warp_n * 64 + nf * 8 + (lane & 3) * 2;
        bcol[nf] = *(const float2*)(bias + col);
    }
    #pragma unroll
    for (int mf = 0; mf < 2; ++mf) {
        int r0 = rowBase + warp_m * 32 + mf * 16 + (lane >> 2);
        #pragma unroll
        for (int h = 0; h < 2; ++h) {
            int row = r0 + h * 8;
            if (row < N) {
                #pragma unroll
                for (int nf = 0; nf < 8; ++nf) {
                    int col = warp_n * 64 + nf * 8 + (lane & 3) * 2;
                    float2 o;
                    o.x = acc[mf][nf][h * 2 + 0] + bcol[nf].x;
                    o.y = acc[mf][nf][h * 2 + 1] + bcol[nf].y;
                    *(float2*)(out + (size_t)row * D + col) = o;
                }
            }
        }
    }
}

// ---------------- launch ----------------
extern "C" void kernel_launch(void* const* d_in, const int* in_sizes, int n_in,
                              void* d_out, int out_size) {
    const float* x     = (const float*)d_in[0];
    const void*  edges =               d_in[1];
    const float* mask  = (const float*)d_in[2];
    const float* gamma = (const float*)d_in[3];
    const float* beta  = (const float*)d_in[4];
    const float* wl    = (const float*)d_in[5];
    const float* bl    = (const float*)d_in[6];
    const float* wr    = (const float*)d_in[7];
    float* out = (float*)d_out;

    int N = in_sizes[0] / D;
    int E = in_sizes[1] / 2;

    static bool inited = false;
    if (!inited) {
        cudaFuncSetAttribute(mma_gemm_kernel,
                             cudaFuncAttributeMaxDynamicSharedMemorySize, GSMEM_TOTAL);
        inited = true;
    }

    int nb = (N + 1023) / 1024;
    int ethreads = E / 2 + 2;
    int cntBlks = (ethreads + 255) / 256;
    int lnBlks = ((N + 1) / 2 + 7) / 8;
    int wBlks = (128 * 256 + 255) / 256;

    prep_kernel<<<cntBlks + lnBlks + wBlks, 256>>>(x, mask, gamma, beta, wl, wr,
                                                   edges, N, E, cntBlks, lnBlks);

    cudaLaunchAttribute pdl[1];
    pdl[0].id = cudaLaunchAttributeProgrammaticStreamSerialization;
    pdl[0].val.programmaticStreamSerializationAllowed = 1;

    {
        cudaLaunchConfig_t cfg = {};
        cfg.gridDim = dim3(nb); cfg.blockDim = dim3(1024);
        cfg.attrs = pdl; cfg.numAttrs = 1;
        cudaLaunchKernelEx(&cfg, scan_kernel, N);
    }
    {
        cudaLaunchConfig_t cfg = {};
        cfg.gridDim = dim3(cntBlks); cfg.blockDim = dim3(256);
        cfg.attrs = pdl; cfg.numAttrs = 1;
        cudaLaunchKernelEx(&cfg, scatter_kernel, (const void*)edges, E,
                           (unsigned long long)N);
    }
    {
        cudaLaunchConfig_t cfg = {};
        cfg.gridDim = dim3((N + 7) / 8); cfg.blockDim = dim3(256);
        cfg.attrs = pdl; cfg.numAttrs = 1;
        cudaLaunchKernelEx(&cfg, aggregate_kernel, N, E);
    }
    {
        cudaLaunchConfig_t cfg = {};
        cfg.gridDim = dim3((N + 127) / 128); cfg.blockDim = dim3(256);
        cfg.dynamicSmemBytes = GSMEM_TOTAL;
        cfg.attrs = pdl; cfg.numAttrs = 1;
        cudaLaunchKernelEx(&cfg, mma_gemm_kernel, (const float*)bl, out, N);
    }
}

// round 17
// speedup vs baseline: 1.0278x; 1.0278x over previous
#include <cuda_runtime.h>
#include <cuda_bf16.h>
#include <cuda_fp16.h>
#include <cstdint>

// ---------------- problem-size constants ----------------
#define MAX_N 50176
#define MAX_E 800000
#define D 128

// ---------------- device scratch ----------------
__device__ __half g_A[(size_t)MAX_N * 256];   // cols [0,128)=agg, [128,256)=h
__device__ __half g_W[128 * 256];             // fused weights [n][k] fp16
__device__ int   g_deg[MAX_N];                // zero at kernel-entry invariant
__device__ int   g_start[MAX_N];
__device__ int   g_cursor[MAX_N];
__device__ int   g_csr[MAX_E];                // stores src*512+256 (byte offset)
__device__ unsigned long long g_scanState[64];

// ---------------- helpers ----------------
#define GRID_WAIT()       asm volatile("griddepcontrol.wait;" ::: "memory")
#define GRID_LAUNCH_DEP() asm volatile("griddepcontrol.launch_dependents;" ::: "memory")

__device__ __forceinline__ uint32_t smem_u32(const void* p) {
    uint32_t a;
    asm("{ .reg .u64 t; cvta.to.shared.u64 t, %1; cvt.u32.u64 %0, t; }" : "=r"(a) : "l"(p));
    return a;
}

__device__ __forceinline__ void ldmat_x4(uint32_t addr, uint32_t* r) {
    asm volatile("ldmatrix.sync.aligned.m8n8.x4.shared.b16 {%0,%1,%2,%3}, [%4];"
                 : "=r"(r[0]), "=r"(r[1]), "=r"(r[2]), "=r"(r[3]) : "r"(addr));
}

__device__ __forceinline__ void mma16816(float* d, const uint32_t* a,
                                         uint32_t b0, uint32_t b1) {
    asm volatile(
        "mma.sync.aligned.m16n8k16.row.col.f32.f16.f16.f32 "
        "{%0,%1,%2,%3}, {%4,%5,%6,%7}, {%8,%9}, {%0,%1,%2,%3};"
        : "+f"(d[0]), "+f"(d[1]), "+f"(d[2]), "+f"(d[3])
        : "r"(a[0]), "r"(a[1]), "r"(a[2]), "r"(a[3]), "r"(b0), "r"(b1));
}

#define CP_ASYNC16(dst, src) \
    asm volatile("cp.async.cg.shared.global [%0], [%1], 16;" :: "r"(dst), "l"(src))
#define CP_COMMIT() asm volatile("cp.async.commit_group;")
#define CP_WAIT(n)  asm volatile("cp.async.wait_group %0;" :: "n"(n))

__device__ __forceinline__ int probe_is32(const void* edges, unsigned long long Nval) {
    const unsigned long long* e = (const unsigned long long*)edges;
    int bad = 0;
    if (threadIdx.x < 64) bad = (e[threadIdx.x] >= Nval);
    return __syncthreads_or(bad);
}

__device__ __forceinline__ __half2 u2h(uint32_t u) { return *(const __half2*)&u; }

// ---------------- count (one vector element per thread) ----------------
__global__ void count_deg_kernel(const void* __restrict__ edges, int E,
                                 unsigned long long Nval) {
    GRID_LAUNCH_DEP();
    int is32 = probe_is32(edges, Nval);
    long long gtid = blockIdx.x * (long long)blockDim.x + threadIdx.x;
    if (is32) {
        const int* dst = (const int*)edges + E;
        int n4 = E >> 2;
        if (gtid < n4) {
            int4 v = ((const int4*)dst)[gtid];
            atomicAdd(&g_deg[v.x], 1);
            atomicAdd(&g_deg[v.y], 1);
            atomicAdd(&g_deg[v.z], 1);
            atomicAdd(&g_deg[v.w], 1);
        }
        int tail = E & 3;
        if (gtid >= n4 && gtid < n4 + tail)
            atomicAdd(&g_deg[dst[(E & ~3) + (int)(gtid - n4)]], 1);
    } else {
        const long long* dst = (const long long*)edges + E;
        int n2 = E >> 1;
        if (gtid < n2) {
            longlong2 v = ((const longlong2*)dst)[gtid];
            atomicAdd(&g_deg[(int)v.x], 1);
            atomicAdd(&g_deg[(int)v.y], 1);
        }
        if ((E & 1) && gtid == n2) atomicAdd(&g_deg[(int)dst[E - 1]], 1);
    }
}

// ---------------- LN + W convert (disjoint block ranges) ----------------
__global__ void lnw_kernel(const float* __restrict__ x,
                           const float* __restrict__ mask,
                           const float* __restrict__ gamma,
                           const float* __restrict__ beta,
                           const float* __restrict__ wl,
                           const float* __restrict__ wr,
                           int N, int lnBlks) {
    int b = blockIdx.x;
    if (b < lnBlks) {
        int warp = (b * blockDim.x + threadIdx.x) >> 5;
        int lane = threadIdx.x & 31;
        int row0 = warp * 2;
        if (row0 >= N) return;
        bool has1 = (row0 + 1) < N;
        float4 v0 = ((const float4*)(x + (size_t)row0 * D))[lane];
        float4 v1 = has1 ? ((const float4*)(x + (size_t)(row0 + 1) * D))[lane]
                         : make_float4(0.f, 0.f, 0.f, 0.f);
        float4 m0 = ((const float4*)(mask + (size_t)row0 * D))[lane];
        float4 m1 = has1 ? ((const float4*)(mask + (size_t)(row0 + 1) * D))[lane]
                         : make_float4(0.f, 0.f, 0.f, 0.f);
        float4 g = ((const float4*)gamma)[lane];
        float4 bb = ((const float4*)beta)[lane];

        float s0 = v0.x + v0.y + v0.z + v0.w;
        float q0 = v0.x * v0.x + v0.y * v0.y + v0.z * v0.z + v0.w * v0.w;
        float s1 = v1.x + v1.y + v1.z + v1.w;
        float q1 = v1.x * v1.x + v1.y * v1.y + v1.z * v1.z + v1.w * v1.w;
        #pragma unroll
        for (int o = 16; o; o >>= 1) {
            s0 += __shfl_xor_sync(0xffffffffu, s0, o);
            q0 += __shfl_xor_sync(0xffffffffu, q0, o);
            s1 += __shfl_xor_sync(0xffffffffu, s1, o);
            q1 += __shfl_xor_sync(0xffffffffu, q1, o);
        }
        float mu0  = s0 * (1.0f / D);
        float inv0 = rsqrtf(q0 * (1.0f / D) - mu0 * mu0 + 1e-5f);
        float mu1  = s1 * (1.0f / D);
        float inv1 = rsqrtf(q1 * (1.0f / D) - mu1 * mu1 + 1e-5f);

        float2 p0, p1;
        p0.x = fmaxf((v0.x - mu0) * inv0 * g.x + bb.x, 0.0f) * m0.x;
        p0.y = fmaxf((v0.y - mu0) * inv0 * g.y + bb.y, 0.0f) * m0.y;
        p1.x = fmaxf((v0.z - mu0) * inv0 * g.z + bb.z, 0.0f) * m0.z;
        p1.y = fmaxf((v0.w - mu0) * inv0 * g.w + bb.w, 0.0f) * m0.w;
        __half2* dst0 = (__half2*)(g_A + (size_t)row0 * 256 + 128 + lane * 4);
        dst0[0] = __float22half2_rn(p0);
        dst0[1] = __float22half2_rn(p1);
        if (has1) {
            p0.x = fmaxf((v1.x - mu1) * inv1 * g.x + bb.x, 0.0f) * m1.x;
            p0.y = fmaxf((v1.y - mu1) * inv1 * g.y + bb.y, 0.0f) * m1.y;
            p1.x = fmaxf((v1.z - mu1) * inv1 * g.z + bb.z, 0.0f) * m1.z;
            p1.y = fmaxf((v1.w - mu1) * inv1 * g.w + bb.w, 0.0f) * m1.w;
            __half2* dst1 = (__half2*)(g_A + (size_t)(row0 + 1) * 256 + 128 + lane * 4);
            dst1[0] = __float22half2_rn(p0);
            dst1[1] = __float22half2_rn(p1);
        }
        return;
    }
    int idx = (b - lnBlks) * blockDim.x + threadIdx.x;
    if (idx < 128 * 256) {
        int n = idx >> 8;
        int k = idx & 255;
        float v = (k < 128) ? wl[n * 128 + k] : wr[n * 128 + (k - 128)];
        g_W[idx] = __float2half_rn(v);
    }
}

// ---------------- single-pass decoupled-lookback scan ----------------
__global__ void scan_kernel(int N) {
    GRID_WAIT();
    GRID_LAUNCH_DEP();
    __shared__ int ws[32];
    __shared__ int s_prefix;
    __shared__ int s_total;
    int b = blockIdx.x;
    int i = b * 1024 + threadIdx.x;
    int lane = threadIdx.x & 31, wid = threadIdx.x >> 5;

    int v = (i < N) ? g_deg[i] : 0;
    if (i < N) g_deg[i] = 0;
    int incl = v;
    #pragma unroll
    for (int o = 1; o < 32; o <<= 1) {
        int t = __shfl_up_sync(0xffffffffu, incl, o);
        if (lane >= o) incl += t;
    }
    if (lane == 31) ws[wid] = incl;
    __syncthreads();
    if (wid == 0) {
        int sv = ws[lane];
        int in2 = sv;
        #pragma unroll
        for (int o = 1; o < 32; o <<= 1) {
            int t = __shfl_up_sync(0xffffffffu, in2, o);
            if (lane >= o) in2 += t;
        }
        ws[lane] = in2 - sv;
    }
    __syncthreads();
    int excl = incl - v + ws[wid];
    if (threadIdx.x == 1023) s_total = excl + v;
    __syncthreads();
    int blockSum = s_total;

    if (threadIdx.x == 0) {
        unsigned long long pack = b == 0
            ? ((2ULL << 32) | (unsigned)blockSum)
            : ((1ULL << 32) | (unsigned)blockSum);
        atomicExch(&g_scanState[b], pack);
    }

    if (wid == 0 && b > 0) {
        long long run = 0;
        int j = b - 1;
        while (true) {
            int idx = j - lane;
            unsigned long long s;
            unsigned status;
            do {
                s = (idx >= 0) ? atomicAdd(&g_scanState[idx], 0ULL)
                               : (1ULL << 32);
                status = (unsigned)(s >> 32);
            } while (__any_sync(0xffffffffu, status == 0));
            unsigned val = (unsigned)s;
            unsigned pmask = __ballot_sync(0xffffffffu, status == 2);
            if (pmask) {
                int fl = __ffs(pmask) - 1;
                long long c = (lane <= fl) ? (long long)val : 0;
                #pragma unroll
                for (int o = 16; o; o >>= 1) c += __shfl_xor_sync(0xffffffffu, c, o);
                run += c;
                break;
            } else {
                long long c = (idx >= 0) ? (long long)val : 0;
                #pragma unroll
                for (int o = 16; o; o >>= 1) c += __shfl_xor_sync(0xffffffffu, c, o);
                run += c;
                j -= 32;
            }
        }
        if (lane == 0) {
            atomicExch(&g_scanState[b], (2ULL << 32) | (unsigned)(run + blockSum));
            s_prefix = (int)run;
        }
    }
    if (b == 0 && threadIdx.x == 0) s_prefix = 0;
    __syncthreads();
    if (i < N) {
        int st = excl + s_prefix;
        g_start[i] = st;
        g_cursor[i] = st;
    }
}

// ---------------- scatter: stores src*512+256 (byte offset of h row) --------
__global__ void scatter_kernel(const void* __restrict__ edges, int E,
                               unsigned long long Nval) {
    GRID_WAIT();
    if (blockIdx.x == 0 && threadIdx.x < 64) g_scanState[threadIdx.x] = 0ULL;
    int is32 = probe_is32(edges, Nval);
    long long gtid = blockIdx.x * (long long)blockDim.x + threadIdx.x;
    if (is32) {
        int n4 = E >> 2;
        if (gtid < n4) {
            int4 sv = ((const int4*)edges)[gtid];
            int4 dv = ((const int4*)((const int*)edges + E))[gtid];
            g_csr[atomicAdd(&g_cursor[dv.x], 1)] = (sv.x << 9) + 256;
            g_csr[atomicAdd(&g_cursor[dv.y], 1)] = (sv.y << 9) + 256;
            g_csr[atomicAdd(&g_cursor[dv.z], 1)] = (sv.z << 9) + 256;
            g_csr[atomicAdd(&g_cursor[dv.w], 1)] = (sv.w << 9) + 256;
        }
        int tail = E & 3;
        if (gtid >= n4 && gtid < n4 + tail) {
            int e = (E & ~3) + (int)(gtid - n4);
            int src = ((const int*)edges)[e];
            int dst = ((const int*)edges)[E + e];
            g_csr[atomicAdd(&g_cursor[dst], 1)] = (src << 9) + 256;
        }
    } else {
        int n2 = E >> 1;
        if (gtid < n2) {
            longlong2 sv = ((const longlong2*)edges)[gtid];
            longlong2 dv = ((const longlong2*)((const long long*)edges + E))[gtid];
            g_csr[atomicAdd(&g_cursor[(int)dv.x], 1)] = ((int)sv.x << 9) + 256;
            g_csr[atomicAdd(&g_cursor[(int)dv.y], 1)] = ((int)sv.y << 9) + 256;
        }
        if ((E & 1) && gtid == n2) {
            int src = (int)((const long long*)edges)[E - 1];
            int dst = (int)((const long long*)edges)[2 * E - 1];
            g_csr[atomicAdd(&g_cursor[dst], 1)] = (src << 9) + 256;
        }
    }
}

// ---------------- aggregation: depth-8 fp16 tree (plain launch) ------------
__global__ void aggregate_kernel(int N, int E) {
    GRID_LAUNCH_DEP();        // lets gemm's pre-phase (B + h cols) start early
    int warp = (blockIdx.x * blockDim.x + threadIdx.x) >> 5;
    int lane = threadIdx.x & 31;
    if (warp >= N) return;
    int st = g_start[warp];
    int en = (warp + 1 < N) ? g_start[warp + 1] : E;
    int d  = en - st;
    const char* hb = (const char*)g_A + lane * 8;
    float2 acc0 = make_float2(0.f, 0.f);
    float2 acc1 = make_float2(0.f, 0.f);
    int j = st;
    for (; j + 8 <= en; j += 8) {
        int o0 = g_csr[j],     o1 = g_csr[j + 1], o2 = g_csr[j + 2], o3 = g_csr[j + 3];
        int o4 = g_csr[j + 4], o5 = g_csr[j + 5], o6 = g_csr[j + 6], o7 = g_csr[j + 7];
        uint2 v0 = *(const uint2*)(hb + o0);
        uint2 v1 = *(const uint2*)(hb + o1);
        uint2 v2 = *(const uint2*)(hb + o2);
        uint2 v3 = *(const uint2*)(hb + o3);
        uint2 v4 = *(const uint2*)(hb + o4);
        uint2 v5 = *(const uint2*)(hb + o5);
        uint2 v6 = *(const uint2*)(hb + o6);
        uint2 v7 = *(const uint2*)(hb + o7);
        __half2 qx = __hadd2(
            __hadd2(__hadd2(u2h(v0.x), u2h(v1.x)), __hadd2(u2h(v2.x), u2h(v3.x))),
            __hadd2(__hadd2(u2h(v4.x), u2h(v5.x)), __hadd2(u2h(v6.x), u2h(v7.x))));
        __half2 qy = __hadd2(
            __hadd2(__hadd2(u2h(v0.y), u2h(v1.y)), __hadd2(u2h(v2.y), u2h(v3.y))),
            __hadd2(__hadd2(u2h(v4.y), u2h(v5.y)), __hadd2(u2h(v6.y), u2h(v7.y))));
        float2 f;
        f = __half22float2(qx); acc0.x += f.x; acc0.y += f.y;
        f = __half22float2(qy); acc1.x += f.x; acc1.y += f.y;
    }
    if (j + 4 <= en) {
        int o0 = g_csr[j], o1 = g_csr[j + 1], o2 = g_csr[j + 2], o3 = g_csr[j + 3];
        uint2 v0 = *(const uint2*)(hb + o0);
        uint2 v1 = *(const uint2*)(hb + o1);
        uint2 v2 = *(const uint2*)(hb + o2);
        uint2 v3 = *(const uint2*)(hb + o3);
        __half2 qx = __hadd2(__hadd2(u2h(v0.x), u2h(v1.x)), __hadd2(u2h(v2.x), u2h(v3.x)));
        __half2 qy = __hadd2(__hadd2(u2h(v0.y), u2h(v1.y)), __hadd2(u2h(v2.y), u2h(v3.y)));
        float2 f;
        f = __half22float2(qx); acc0.x += f.x; acc0.y += f.y;
        f = __half22float2(qy); acc1.x += f.x; acc1.y += f.y;
        j += 4;
    }
    for (; j < en; ++j) {
        uint2 v = *(const uint2*)(hb + g_csr[j]);
        float2 a = __half22float2(u2h(v.x));
        float2 b = __half22float2(u2h(v.y));
        acc0.x += a.x; acc0.y += a.y; acc1.x += b.x; acc1.y += b.y;
    }
    float invd = 1.0f / fmaxf((float)d, 1.0f);
    acc0.x *= invd; acc0.y *= invd; acc1.x *= invd; acc1.y *= invd;
    __half2 h0 = __float22half2_rn(acc0);
    __half2 h1 = __float22half2_rn(acc1);
    uint2 pk;
    pk.x = *(uint32_t*)&h0;
    pk.y = *(uint32_t*)&h1;
    *(uint2*)((char*)g_A + (size_t)warp * 512 + lane * 8) = pk;
}

// ---------------- fp16 mma GEMM: h-chunks overlap aggregate via PDL --------
#define B_OFF  0
#define A0_OFF 65536
#define ABUF_SZ 16384
#define GSMEM_TOTAL (65536 + 2 * ABUF_SZ)

__global__ __launch_bounds__(256) void mma_gemm_kernel(const float* __restrict__ bias,
                                                       float* __restrict__ out, int N) {
    extern __shared__ char smem[];
    uint32_t sb = smem_u32(smem);
    int tid = threadIdx.x;
    int lane = tid & 31;
    int wid = tid >> 5;
    int warp_m = wid & 3;
    int warp_n = wid >> 2;
    int rowBase = blockIdx.x * 128;

    for (int idx = tid; idx < 4096; idx += 256) {
        int r  = idx >> 5;
        int ck = idx & 31;
        uint32_t off = (uint32_t)r * 512 + ((uint32_t)(ck ^ (r & 7)) << 4);
        CP_ASYNC16(sb + B_OFF + off, (const char*)(g_W + (size_t)r * 256 + ck * 8));
    }
    #define STAGE_A(c, buf)                                                        \
        for (int idx = tid; idx < 1024; idx += 256) {                              \
            int r  = idx >> 3;                                                     \
            int ck = idx & 7;                                                      \
            CP_ASYNC16(sb + A0_OFF + (buf) * ABUF_SZ + r * 128                     \
                           + ((uint32_t)(ck ^ (r & 7)) << 4),                      \
                       (const char*)(g_A + (size_t)(rowBase + r) * 256             \
                                     + (c) * 64 + ck * 8));                        \
        }
    STAGE_A(2, 0);
    CP_COMMIT();
    STAGE_A(3, 1);
    CP_COMMIT();

    float acc[2][8][4];
    #pragma unroll
    for (int i = 0; i < 2; i++)
        #pragma unroll
        for (int j = 0; j < 8; j++)
            #pragma unroll
            for (int q = 0; q < 4; q++) acc[i][j][q] = 0.0f;

    int aRow = (lane & 7) + ((lane >> 3) & 1) * 8;
    int aK8  = (lane >> 4) * 8;
    int bN   = (lane & 7) + (lane >> 4) * 8;
    int bK8  = ((lane >> 3) & 1) * 8;

    #define COMPUTE_CHUNK(gc, buf)                                                 \
        {                                                                          \
            uint32_t abase = sb + A0_OFF + (buf) * ABUF_SZ;                        \
            _Pragma("unroll")                                                      \
            for (int ks = 0; ks < 4; ++ks) {                                       \
                int kk = ks * 16;                                                  \
                uint32_t a[2][4];                                                  \
                _Pragma("unroll")                                                  \
                for (int mf = 0; mf < 2; ++mf) {                                   \
                    int row = warp_m * 32 + mf * 16 + aRow;                        \
                    int kA  = kk + aK8;                                            \
                    uint32_t addr = abase + (uint32_t)row * 128                    \
                                  + ((uint32_t)(((kA >> 3) ^ (row & 7))) << 4);    \
                    ldmat_x4(addr, a[mf]);                                         \
                }                                                                  \
                int gk = (gc) * 64 + kk;                                           \
                _Pragma("unroll")                                                  \
                for (int j = 0; j < 4; ++j) {                                      \
                    int n  = warp_n * 64 + j * 16 + bN;                            \
                    int kB = gk + bK8;                                             \
                    uint32_t addr = sb + B_OFF + (uint32_t)n * 512                 \
                                  + ((uint32_t)(((kB >> 3) ^ (n & 7))) << 4);      \
                    uint32_t b[4];                                                 \
                    ldmat_x4(addr, b);                                             \
                    mma16816(acc[0][2 * j],     a[0], b[0], b[1]);                 \
                    mma16816(acc[0][2 * j + 1], a[0], b[2], b[3]);                 \
                    mma16816(acc[1][2 * j],     a[1], b[0], b[1]);                 \
                    mma16816(acc[1][2 * j + 1], a[1], b[2], b[3]);                 \
                }                                                                  \
            }                                                                      \
        }

    CP_WAIT(1);
    __syncthreads();
    COMPUTE_CHUNK(2, 0);
    CP_WAIT(0);
    __syncthreads();
    COMPUTE_CHUNK(3, 1);
    __syncthreads();

    GRID_WAIT();
    STAGE_A(0, 0);
    CP_COMMIT();
    STAGE_A(1, 1);
    CP_COMMIT();
    CP_WAIT(1);
    __syncthreads();
    COMPUTE_CHUNK(0, 0);
    CP_WAIT(0);
    __syncthreads();
    COMPUTE_CHUNK(1, 1);

    float2 bcol[8];
    #pragma unroll
    for (int nf = 0; nf < 8; ++nf) {
        int col = warp_n * 64 + nf * 8 + (lane & 3) * 2;
        bcol[nf] = *(const float2*)(bias + col);
    }
    #pragma unroll
    for (int mf = 0; mf < 2; ++mf) {
        int r0 = rowBase + warp_m * 32 + mf * 16 + (lane >> 2);
        #pragma unroll
        for (int h = 0; h < 2; ++h) {
            int row = r0 + h * 8;
            if (row < N) {
                #pragma unroll
                for (int nf = 0; nf < 8; ++nf) {
                    int col = warp_n * 64 + nf * 8 + (lane & 3) * 2;
                    float2 o;
                    o.x = acc[mf][nf][h * 2 + 0] + bcol[nf].x;
                    o.y = acc[mf][nf][h * 2 + 1] + bcol[nf].y;
                    *(float2*)(out + (size_t)row * D + col) = o;
                }
            }
        }
    }
}

// ---------------- launch ----------------
extern "C" void kernel_launch(void* const* d_in, const int* in_sizes, int n_in,
                              void* d_out, int out_size) {
    const float* x     = (const float*)d_in[0];
    const void*  edges =               d_in[1];
    const float* mask  = (const float*)d_in[2];
    const float* gamma = (const float*)d_in[3];
    const float* beta  = (const float*)d_in[4];
    const float* wl    = (const float*)d_in[5];
    const float* bl    = (const float*)d_in[6];
    const float* wr    = (const float*)d_in[7];
    float* out = (float*)d_out;

    int N = in_sizes[0] / D;
    int E = in_sizes[1] / 2;

    static cudaStream_t s2 = nullptr;
    static cudaEvent_t evRoot = nullptr, evB = nullptr;
    if (!s2) {
        cudaStreamCreateWithFlags(&s2, cudaStreamNonBlocking);
        cudaEventCreateWithFlags(&evRoot, cudaEventDisableTiming);
        cudaEventCreateWithFlags(&evB, cudaEventDisableTiming);
        cudaFuncSetAttribute(mma_gemm_kernel,
                             cudaFuncAttributeMaxDynamicSharedMemorySize, GSMEM_TOTAL);
    }

    int nb = (N + 1023) / 1024;
    int ethreads = E / 2 + 2;
    int cntBlks = (ethreads + 255) / 256;
    int lnBlks = ((N + 1) / 2 + 7) / 8;
    int wBlks = (128 * 256 + 255) / 256;

    cudaLaunchAttribute pdl[1];
    pdl[0].id = cudaLaunchAttributeProgrammaticStreamSerialization;
    pdl[0].val.programmaticStreamSerializationAllowed = 1;

    // ---- fork: CSR chain on s2 with internal PDL ----
    cudaEventRecord(evRoot, 0);
    cudaStreamWaitEvent(s2, evRoot, 0);
    count_deg_kernel<<<cntBlks, 256, 0, s2>>>(edges, E, (unsigned long long)N);
    {
        cudaLaunchConfig_t cfg = {};
        cfg.gridDim = dim3(nb); cfg.blockDim = dim3(1024); cfg.stream = s2;
        cfg.attrs = pdl; cfg.numAttrs = 1;
        cudaLaunchKernelEx(&cfg, scan_kernel, N);
    }
    {
        cudaLaunchConfig_t cfg = {};
        cfg.gridDim = dim3(cntBlks); cfg.blockDim = dim3(256); cfg.stream = s2;
        cfg.attrs = pdl; cfg.numAttrs = 1;
        cudaLaunchKernelEx(&cfg, scatter_kernel, (const void*)edges, E,
                           (unsigned long long)N);
    }
    cudaEventRecord(evB, s2);

    // ---- main stream: LN + W concurrent with CSR chain ----
    lnw_kernel<<<lnBlks + wBlks, 256>>>(x, mask, gamma, beta, wl, wr, N, lnBlks);

    // ---- join, aggregate (plain), then gemm (PDL overlap with aggregate) ----
    cudaStreamWaitEvent(0, evB, 0);
    aggregate_kernel<<<(N + 7) / 8, 256>>>(N, E);
    {
        cudaLaunchConfig_t cfg = {};
        cfg.gridDim = dim3((N + 127) / 128); cfg.blockDim = dim3(256);
        cfg.dynamicSmemBytes = GSMEM_TOTAL;
        cfg.attrs = pdl; cfg.numAttrs = 1;
        cudaLaunchKernelEx(&cfg, mma_gemm_kernel, (const float*)bl, out, N);
    }
}